// round 1
// baseline (speedup 1.0000x reference)
#include <cuda_runtime.h>
#include <math.h>

#define B_    8192
#define OBSD  256
#define ACTD  32
#define HIDD  512
#define PEXP  8

// ---------- scratch (no allocations allowed) ----------
__device__ __align__(16) float g_buf0[B_ * HIDD];
__device__ __align__(16) float g_buf1[B_ * HIDD];
__device__ __align__(16) float g_blend[B_ * PEXP];

// ---------- packed f32x2 helpers (Blackwell FFMA2 pipe) ----------
__device__ __forceinline__ unsigned long long pack2(float lo, float hi) {
    unsigned long long r;
    asm("mov.b64 %0, {%1,%2};" : "=l"(r) : "f"(lo), "f"(hi));
    return r;
}
__device__ __forceinline__ void unpack2(unsigned long long v, float& lo, float& hi) {
    asm("mov.b64 {%0,%1}, %2;" : "=f"(lo), "=f"(hi) : "l"(v));
}
__device__ __forceinline__ void fma2(unsigned long long& d, unsigned long long a, unsigned long long b) {
    asm("fma.rn.f32x2 %0, %1, %2, %0;" : "+l"(d) : "l"(a), "l"(b));
}
__device__ __forceinline__ unsigned long long add2(unsigned long long a, unsigned long long b) {
    unsigned long long r;
    asm("add.rn.f32x2 %0, %1, %2;" : "=l"(r) : "l"(a), "l"(b));
    return r;
}

__device__ __forceinline__ const float* pick_src(int sel, const float* ext) {
    if (sel == 0) return g_buf0;
    if (sel == 1) return g_buf1;
    return ext;
}
__device__ __forceinline__ float* pick_dst(int sel, float* ext) {
    if (sel == 0) return g_buf0;
    if (sel == 1) return g_buf1;
    return ext;
}

// ------------------------------------------------------------------
// Blended GEMM:  C[m,n] = epi( sum_p blend[m,p] * ( A[m,:] . W[p,n,:] + bias[p,n] ) )
// NEXP = 1 -> plain GEMM+bias (gate layers, blend ignored, weight 1)
// EPI  = 0 -> relu ; EPI = 1 -> actor head (mu passthrough / std = exp(3.5*tanh - 1.5))
// Tiles: BM=128, BN=64, BK=16, 256 threads, 4x8 per-thread microtile, f32x2 FMAs.
// ------------------------------------------------------------------
template <int NEXP, int EPI>
__global__ __launch_bounds__(256, 2)
void blend_gemm(const float* __restrict__ Aext, int Asel,
                const float* __restrict__ W,
                const float* __restrict__ bias,
                float* __restrict__ Cext, int Csel,
                int M, int N, int K)
{
    constexpr int BM = 128, BN = 64, BK = 16;

    __shared__ __align__(16) float As[BK][BM];  // As[k][m]
    __shared__ __align__(16) float Bs[BK][BN];  // Bs[k][n]

    const float* A = pick_src(Asel, Aext);
    float*       C = pick_dst(Csel, Cext);

    const int tid  = threadIdx.x;
    const int trow = tid >> 3;   // 0..31
    const int tcol = tid & 7;    // 0..7
    const int row0 = blockIdx.y * BM;
    const int rowBase = row0 + trow * 4;
    const int colBase = blockIdx.x * BN + tcol * 8;

    // A/B load mapping: each thread loads float4(s)
    const int lm  = tid >> 2;        // 0..63
    const int lk4 = (tid & 3) * 4;   // 0,4,8,12

    unsigned long long accT[4][4];
#pragma unroll
    for (int i = 0; i < 4; i++)
#pragma unroll
        for (int j = 0; j < 4; j++) accT[i][j] = 0ULL;

    const int nkt = K / BK;

#pragma unroll 1
    for (int p = 0; p < NEXP; p++) {
        unsigned long long accP[4][4];
#pragma unroll
        for (int i = 0; i < 4; i++)
#pragma unroll
            for (int j = 0; j < 4; j++) accP[i][j] = 0ULL;

        const float* Wp = W + ((size_t)p * N + blockIdx.x * BN) * K;

#pragma unroll 1
        for (int kt = 0; kt < nkt; kt++) {
            const int k0 = kt * BK;
            __syncthreads();   // previous tile fully consumed

            // load A tile: rows lm and lm+64
            {
                const float4 a0 = *(const float4*)&A[(size_t)(row0 + lm) * K + k0 + lk4];
                const float4 a1 = *(const float4*)&A[(size_t)(row0 + lm + 64) * K + k0 + lk4];
                As[lk4 + 0][lm] = a0.x;  As[lk4 + 1][lm] = a0.y;
                As[lk4 + 2][lm] = a0.z;  As[lk4 + 3][lm] = a0.w;
                As[lk4 + 0][lm + 64] = a1.x;  As[lk4 + 1][lm + 64] = a1.y;
                As[lk4 + 2][lm + 64] = a1.z;  As[lk4 + 3][lm + 64] = a1.w;
            }
            // load B tile: row lm (n index), same lk4
            {
                const float4 b0 = *(const float4*)&Wp[(size_t)lm * K + k0 + lk4];
                Bs[lk4 + 0][lm] = b0.x;  Bs[lk4 + 1][lm] = b0.y;
                Bs[lk4 + 2][lm] = b0.z;  Bs[lk4 + 3][lm] = b0.w;
            }
            __syncthreads();

#pragma unroll
            for (int k = 0; k < BK; k++) {
                const float4 av = *(const float4*)&As[k][trow * 4];
                const ulonglong2 bv01 = *(const ulonglong2*)&Bs[k][tcol * 8];
                const ulonglong2 bv23 = *(const ulonglong2*)&Bs[k][tcol * 8 + 4];
                unsigned long long bv[4] = {bv01.x, bv01.y, bv23.x, bv23.y};
                unsigned long long ad[4] = {pack2(av.x, av.x), pack2(av.y, av.y),
                                            pack2(av.z, av.z), pack2(av.w, av.w)};
#pragma unroll
                for (int i = 0; i < 4; i++)
#pragma unroll
                    for (int j = 0; j < 4; j++)
                        fma2(accP[i][j], ad[i], bv[j]);
            }
        }

        // fold: accT += blend[row,p] * (accP + bias[p, col])
        const unsigned long long* bb2 =
            (const unsigned long long*)(bias + (size_t)p * N + colBase);
        unsigned long long bb[4] = {bb2[0], bb2[1], bb2[2], bb2[3]};

        if (NEXP == 1) {
#pragma unroll
            for (int i = 0; i < 4; i++)
#pragma unroll
                for (int j = 0; j < 4; j++)
                    accT[i][j] = add2(accP[i][j], bb[j]);
        } else {
#pragma unroll
            for (int i = 0; i < 4; i++) {
                const float bl = g_blend[(size_t)(rowBase + i) * PEXP + p];
                const unsigned long long bld = pack2(bl, bl);
#pragma unroll
                for (int j = 0; j < 4; j++) {
                    unsigned long long t = add2(accP[i][j], bb[j]);
                    fma2(accT[i][j], bld, t);
                }
            }
        }
    }

    // epilogue + store
    const int half = N >> 1;
#pragma unroll
    for (int i = 0; i < 4; i++) {
        const int r = rowBase + i;
        float o[8];
        unpack2(accT[i][0], o[0], o[1]);
        unpack2(accT[i][1], o[2], o[3]);
        unpack2(accT[i][2], o[4], o[5]);
        unpack2(accT[i][3], o[6], o[7]);
        if (EPI == 0) {
#pragma unroll
            for (int j = 0; j < 8; j++) o[j] = fmaxf(o[j], 0.0f);
        } else {
#pragma unroll
            for (int j = 0; j < 8; j++) {
                if (colBase + j >= half) {
                    const float t = tanhf(o[j]);
                    o[j] = expf(3.5f * t - 1.5f);
                }
            }
        }
        float4* dst = (float4*)&C[(size_t)r * N + colBase];
        dst[0] = make_float4(o[0], o[1], o[2], o[3]);
        dst[1] = make_float4(o[4], o[5], o[6], o[7]);
    }
}

// ------------------------------------------------------------------
// Gate head: logits = h @ gw2^T + gb2 ; blend = softmax(logits)
// One warp per row; lanes split K, conflict-free smem broadcast of gw2.
// ------------------------------------------------------------------
__global__ __launch_bounds__(256)
void gate2_softmax(const float* __restrict__ gw2, const float* __restrict__ gb2)
{
    __shared__ float ws[PEXP * HIDD];   // 16 KB
    const int tid = threadIdx.x;
    for (int i = tid; i < PEXP * HIDD; i += blockDim.x) ws[i] = gw2[i];
    __syncthreads();

    const int warp = tid >> 5;
    const int lane = tid & 31;
    const int row  = blockIdx.x * 8 + warp;
    const float* hr = g_buf1 + (size_t)row * HIDD;

    float acc[PEXP];
#pragma unroll
    for (int p = 0; p < PEXP; p++) acc[p] = 0.0f;

#pragma unroll
    for (int i = 0; i < HIDD / 32; i++) {
        const float hv = hr[i * 32 + lane];
#pragma unroll
        for (int p = 0; p < PEXP; p++)
            acc[p] = fmaf(hv, ws[p * HIDD + i * 32 + lane], acc[p]);
    }
#pragma unroll
    for (int p = 0; p < PEXP; p++) {
#pragma unroll
        for (int off = 16; off > 0; off >>= 1)
            acc[p] += __shfl_xor_sync(0xffffffffu, acc[p], off);
    }

    float l[PEXP], m = -1e30f;
#pragma unroll
    for (int p = 0; p < PEXP; p++) { l[p] = acc[p] + gb2[p]; m = fmaxf(m, l[p]); }
    float s = 0.0f;
#pragma unroll
    for (int p = 0; p < PEXP; p++) { l[p] = expf(l[p] - m); s += l[p]; }
    const float inv = 1.0f / s;

    float myv = 0.0f;
#pragma unroll
    for (int p = 0; p < PEXP; p++)
        if (lane == p) myv = l[p] * inv;
    if (lane < PEXP) g_blend[(size_t)row * PEXP + lane] = myv;
}

// ------------------------------------------------------------------
extern "C" void kernel_launch(void* const* d_in, const int* in_sizes, int n_in,
                              void* d_out, int out_size)
{
    const float* obs = (const float*)d_in[0];
    const float* gw0 = (const float*)d_in[1];
    const float* gb0 = (const float*)d_in[2];
    const float* gw1 = (const float*)d_in[3];
    const float* gb1 = (const float*)d_in[4];
    const float* gw2 = (const float*)d_in[5];
    const float* gb2 = (const float*)d_in[6];
    const float* ew0 = (const float*)d_in[7];
    const float* eb0 = (const float*)d_in[8];
    const float* ew1 = (const float*)d_in[9];
    const float* eb1 = (const float*)d_in[10];
    const float* ew2 = (const float*)d_in[11];
    const float* eb2 = (const float*)d_in[12];
    float* out = (float*)d_out;

    const dim3 blk(256);
    // gate layer 0: obs -> g_buf0  (M=8192, N=512, K=256)
    blend_gemm<1, 0><<<dim3(HIDD / 64, B_ / 128), blk>>>(obs, -1, gw0, gb0, nullptr, 0, B_, HIDD, OBSD);
    // gate layer 1: g_buf0 -> g_buf1  (N=512, K=512)
    blend_gemm<1, 0><<<dim3(HIDD / 64, B_ / 128), blk>>>(nullptr, 0, gw1, gb1, nullptr, 1, B_, HIDD, HIDD);
    // gate head + softmax: g_buf1 -> g_blend
    gate2_softmax<<<B_ / 8, blk>>>(gw2, gb2);
    // expert layer 0: obs -> g_buf0  (P=8, N=512, K=256)
    blend_gemm<PEXP, 0><<<dim3(HIDD / 64, B_ / 128), blk>>>(obs, -1, ew0, eb0, nullptr, 0, B_, HIDD, OBSD);
    // expert layer 1: g_buf0 -> g_buf1  (P=8, N=512, K=512)
    blend_gemm<PEXP, 0><<<dim3(HIDD / 64, B_ / 128), blk>>>(nullptr, 0, ew1, eb1, nullptr, 1, B_, HIDD, HIDD);
    // expert layer 2 + actor epilogue: g_buf1 -> out  (P=8, N=64, K=512)
    blend_gemm<PEXP, 1><<<dim3(1, B_ / 128), blk>>>(nullptr, 1, ew2, eb2, out, -1, B_, 2 * ACTD, HIDD);
}

// round 3
// speedup vs baseline: 3.7975x; 3.7975x over previous
#include <cuda_runtime.h>
#include <cuda_bf16.h>
#include <cstdint>
#include <math.h>

#define B_    8192
#define OBSD  256
#define ACTD  32
#define HIDD  512
#define PEXP  8

// ======================= scratch (no allocs allowed) =======================
__device__ __align__(16) __nv_bfloat16 d_gw0_h[HIDD * OBSD];
__device__ __align__(16) __nv_bfloat16 d_gw0_l[HIDD * OBSD];
__device__ __align__(16) __nv_bfloat16 d_gw1_h[HIDD * HIDD];
__device__ __align__(16) __nv_bfloat16 d_gw1_l[HIDD * HIDD];
__device__ __align__(16) __nv_bfloat16 d_ew0_h[PEXP * HIDD * OBSD];
__device__ __align__(16) __nv_bfloat16 d_ew0_l[PEXP * HIDD * OBSD];
__device__ __align__(16) __nv_bfloat16 d_ew1_h[PEXP * HIDD * HIDD];
__device__ __align__(16) __nv_bfloat16 d_ew1_l[PEXP * HIDD * HIDD];
__device__ __align__(16) __nv_bfloat16 d_ew2_h[PEXP * 2 * ACTD * HIDD];
__device__ __align__(16) __nv_bfloat16 d_ew2_l[PEXP * 2 * ACTD * HIDD];
__device__ __align__(16) float d_bufA[B_ * HIDD];
__device__ __align__(16) float d_bufB[B_ * HIDD];
__device__ __align__(16) float d_blend[B_ * PEXP];

// ======================= low-level helpers =================================
__device__ __forceinline__ uint32_t smem_u32(const void* p) {
    uint32_t a;
    asm("{ .reg .u64 t; cvta.to.shared.u64 t, %1; cvt.u32.u64 %0, t; }" : "=r"(a) : "l"(p));
    return a;
}
#define CP_ASYNC16(dst, src) \
    asm volatile("cp.async.cg.shared.global [%0], [%1], 16;" :: "r"(dst), "l"(src))
#define CP_COMMIT() asm volatile("cp.async.commit_group;" ::: "memory")
#define CP_WAIT1()  asm volatile("cp.async.wait_group 1;" ::: "memory")

__device__ __forceinline__ void ldsm4(uint32_t* r, uint32_t addr) {
    asm volatile("ldmatrix.sync.aligned.m8n8.x4.shared.b16 {%0,%1,%2,%3}, [%4];"
                 : "=r"(r[0]), "=r"(r[1]), "=r"(r[2]), "=r"(r[3]) : "r"(addr));
}
__device__ __forceinline__ void mma16816(float* c, const uint32_t* a, uint32_t b0, uint32_t b1) {
    asm volatile(
        "mma.sync.aligned.m16n8k16.row.col.f32.bf16.bf16.f32 "
        "{%0,%1,%2,%3}, {%4,%5,%6,%7}, {%8,%9}, {%0,%1,%2,%3};"
        : "+f"(c[0]), "+f"(c[1]), "+f"(c[2]), "+f"(c[3])
        : "r"(a[0]), "r"(a[1]), "r"(a[2]), "r"(a[3]), "r"(b0), "r"(b1));
}

// ======================= fp32 -> bf16 hi/lo split ==========================
__global__ __launch_bounds__(256)
void cvt_hl(const float* __restrict__ src, __nv_bfloat16* __restrict__ hi,
            __nv_bfloat16* __restrict__ lo, int n) {
    int i = blockIdx.x * blockDim.x + threadIdx.x;
    const int stride = gridDim.x * blockDim.x;
    for (; i < n; i += stride) {
        const float v = src[i];
        const __nv_bfloat16 h = __float2bfloat16_rn(v);
        hi[i] = h;
        lo[i] = __float2bfloat16_rn(v - __bfloat162float(h));
    }
}

// ======================= blended MoE GEMM (mma.sync bf16, 3-term) ==========
// Y[m,n] = epi( sum_p (blend[m,p]*A[m,:]) . W[p,n,:]  +  sum_p blend[m,p]*bias[p,n] )
// A fp32 in gmem, scaled+split to bf16 hi/lo on smem fill. W pre-split hi/lo.
// smem row layout (A and B tiles): 128B/row = 64B hi (32 bf16) + 64B lo,
// 16B chunks XOR-swizzled: phys_chunk = chunk ^ (row & 7).
template <int NEXP, int EPI, int BN, int K>
__global__ __launch_bounds__(256, 1)
void moe_gemm(const float* __restrict__ A,
              const __nv_bfloat16* __restrict__ Wh, const __nv_bfloat16* __restrict__ Wl,
              const float* __restrict__ bias, const float* __restrict__ blend,
              float* __restrict__ Y, int NTOT)
{
    constexpr int NC    = K / 32;
    constexpr int NCH   = NEXP * NC;
    constexpr int NT    = BN / 32;             // n16 tiles per warp (2 warps in N)
    constexpr int STAGE = 16384 + BN * 128;    // A tile (16KB) + B tile
    constexpr int BIT   = BN * 8 / 256;        // cp.async iters for B

    extern __shared__ __align__(16) char smem[];
    float* bias_s  = (float*)smem;             // [NEXP*BN]
    float* blend_s = (float*)(smem + 4096);    // [128*8]
    const uint32_t sb = smem_u32(smem);

    const int tid = threadIdx.x;
    const int wid = tid >> 5;
    const int t   = tid & 31;
    const int row0 = blockIdx.y * 128;
    const int n0   = blockIdx.x * BN;

    for (int i = tid; i < NEXP * BN; i += 256)
        bias_s[i] = bias[(size_t)(i / BN) * NTOT + n0 + (i % BN)];
    if (NEXP > 1)
        for (int i = tid; i < 1024; i += 256)
            blend_s[i] = blend[(size_t)(row0 + (i >> 3)) * PEXP + (i & 7)];
    __syncthreads();

    float4 areg[4];

    auto ldgA = [&](int c) {
        const int kk = (c & (NC - 1)) * 32;
#pragma unroll
        for (int it = 0; it < 4; it++) {
            const int idx = tid + it * 256;
            const int ar = idx >> 3, ak = idx & 7;
            areg[it] = *(const float4*)&A[(size_t)(row0 + ar) * K + kk + ak * 4];
        }
    };
    auto storeA = [&](int c, int s) {
        const int p = c / NC;
        char* stA = smem + 8192 + s * STAGE;
#pragma unroll
        for (int it = 0; it < 4; it++) {
            const int idx = tid + it * 256;
            const int ar = idx >> 3, ak = idx & 7;
            const float bl = (NEXP > 1) ? blend_s[ar * 8 + p] : 1.0f;
            const float v0 = areg[it].x * bl, v1 = areg[it].y * bl;
            const float v2 = areg[it].z * bl, v3 = areg[it].w * bl;
            __nv_bfloat162 h01, h23, l01, l23;
            h01.x = __float2bfloat16_rn(v0);  h01.y = __float2bfloat16_rn(v1);
            h23.x = __float2bfloat16_rn(v2);  h23.y = __float2bfloat16_rn(v3);
            l01.x = __float2bfloat16_rn(v0 - __bfloat162float(h01.x));
            l01.y = __float2bfloat16_rn(v1 - __bfloat162float(h01.y));
            l23.x = __float2bfloat16_rn(v2 - __bfloat162float(h23.x));
            l23.y = __float2bfloat16_rn(v3 - __bfloat162float(h23.y));
            const int rb = ar & 7;
            const uint32_t offH = ar * 128 + (((ak >> 1) ^ rb) << 4) + ((ak & 1) << 3);
            const uint32_t offL = ar * 128 + ((((ak >> 1) + 4) ^ rb) << 4) + ((ak & 1) << 3);
            *(uint2*)(stA + offH) = make_uint2(*(uint32_t*)&h01, *(uint32_t*)&h23);
            *(uint2*)(stA + offL) = make_uint2(*(uint32_t*)&l01, *(uint32_t*)&l23);
        }
    };
    auto loadB = [&](int c, int s) {
        const int p = c / NC;
        const int kk = (c & (NC - 1)) * 32;
        const uint32_t stB = sb + 8192 + s * STAGE + 16384;
#pragma unroll
        for (int it = 0; it < BIT; it++) {
            const int idx = tid + it * 256;
            const int br = idx >> 3, bj = idx & 7;
            const __nv_bfloat16* src =
                (bj < 4 ? Wh : Wl) + ((size_t)p * NTOT + n0 + br) * K + kk + (bj & 3) * 8;
            const uint32_t dst = stB + br * 128 + ((bj ^ (br & 7)) << 4);
            CP_ASYNC16(dst, src);
        }
    };

    float acc[2][2 * NT][4];
#pragma unroll
    for (int a = 0; a < 2; a++)
#pragma unroll
        for (int b = 0; b < 2 * NT; b++)
#pragma unroll
            for (int q = 0; q < 4; q++) acc[a][b][q] = 0.0f;

    const int wm = wid >> 1, wn = wid & 1;
    const int aro = ((t >> 3) & 1) * 8 + (t & 7);   // A: row within m16
    const int akg = t >> 4;                          // A: k-half select
    const int bno = ((t >> 4) << 3) + (t & 7);       // B: n within n16
    const int bkg = (t >> 3) & 1;                    // B: k-half select

    auto mmaStage = [&](int s) {
        const uint32_t stA = sb + 8192 + s * STAGE;
        const uint32_t stB = stA + 16384;
#pragma unroll
        for (int kc = 0; kc < 2; kc++) {
            uint32_t ah[2][4], al[2][4];
#pragma unroll
            for (int mt = 0; mt < 2; mt++) {
                const int row = wm * 32 + mt * 16 + aro;
                const int rb = row & 7;
                const int ch = kc * 2 + akg;
                ldsm4(ah[mt], stA + row * 128 + ((ch ^ rb) << 4));
                ldsm4(al[mt], stA + row * 128 + (((ch + 4) ^ rb) << 4));
            }
            uint32_t bh[NT][4], bl[NT][4];
#pragma unroll
            for (int nt = 0; nt < NT; nt++) {
                const int n = wn * (NT * 16) + nt * 16 + bno;
                const int nb = n & 7;
                const int ch = kc * 2 + bkg;
                ldsm4(bh[nt], stB + n * 128 + ((ch ^ nb) << 4));
                ldsm4(bl[nt], stB + n * 128 + (((ch + 4) ^ nb) << 4));
            }
#pragma unroll
            for (int mt = 0; mt < 2; mt++)
#pragma unroll
                for (int nt = 0; nt < NT; nt++) {
                    mma16816(acc[mt][2 * nt + 0], ah[mt], bh[nt][0], bh[nt][1]);
                    mma16816(acc[mt][2 * nt + 1], ah[mt], bh[nt][2], bh[nt][3]);
                    mma16816(acc[mt][2 * nt + 0], ah[mt], bl[nt][0], bl[nt][1]);
                    mma16816(acc[mt][2 * nt + 1], ah[mt], bl[nt][2], bl[nt][3]);
                    mma16816(acc[mt][2 * nt + 0], al[mt], bh[nt][0], bh[nt][1]);
                    mma16816(acc[mt][2 * nt + 1], al[mt], bh[nt][2], bh[nt][3]);
                }
        }
    };

    // -------- pipeline --------
    ldgA(0);
    loadB(0, 0); CP_COMMIT();
    storeA(0, 0);
    ldgA(1);
    loadB(1, 1); CP_COMMIT();
    CP_WAIT1();
    __syncthreads();

#pragma unroll 1
    for (int c = 0; c < NCH; c++) {
        const int cur = c & 1;
        mmaStage(cur);
        __syncthreads();
        if (c + 1 < NCH) storeA(c + 1, cur ^ 1);
        if (c + 2 < NCH) { ldgA(c + 2); loadB(c + 2, cur); }
        CP_COMMIT();
        CP_WAIT1();
        __syncthreads();
    }

    // -------- epilogue --------
    const int tq = t >> 2, tr = t & 3;
#pragma unroll
    for (int mt = 0; mt < 2; mt++) {
#pragma unroll
        for (int h = 0; h < 2; h++) {
            const int r = wm * 32 + mt * 16 + tq + h * 8;
            float blv[PEXP];
            if (NEXP > 1) {
#pragma unroll
                for (int p = 0; p < PEXP; p++) blv[p] = blend_s[r * 8 + p];
            }
#pragma unroll
            for (int nt8 = 0; nt8 < 2 * NT; nt8++) {
                const int col = wn * (NT * 16) + nt8 * 8 + tr * 2;
                float v0 = acc[mt][nt8][h * 2 + 0];
                float v1 = acc[mt][nt8][h * 2 + 1];
                if (NEXP == 1) {
                    v0 += bias_s[col]; v1 += bias_s[col + 1];
                } else {
                    float b0 = 0.0f, b1 = 0.0f;
#pragma unroll
                    for (int p = 0; p < PEXP; p++) {
                        b0 = fmaf(blv[p], bias_s[p * BN + col], b0);
                        b1 = fmaf(blv[p], bias_s[p * BN + col + 1], b1);
                    }
                    v0 += b0; v1 += b1;
                }
                if (EPI == 0) {
                    v0 = fmaxf(v0, 0.0f); v1 = fmaxf(v1, 0.0f);
                } else {
                    if (col >= 32)     v0 = expf(3.5f * tanhf(v0) - 1.5f);
                    if (col + 1 >= 32) v1 = expf(3.5f * tanhf(v1) - 1.5f);
                }
                *(float2*)&Y[(size_t)(row0 + r) * NTOT + n0 + col] = make_float2(v0, v1);
            }
        }
    }
}

// ======================= gate head + softmax ===============================
__global__ __launch_bounds__(256)
void gate2_softmax(const float* __restrict__ h, const float* __restrict__ gw2,
                   const float* __restrict__ gb2, float* __restrict__ blend)
{
    __shared__ float ws[PEXP * HIDD];
    const int tid = threadIdx.x;
    for (int i = tid; i < PEXP * HIDD; i += blockDim.x) ws[i] = gw2[i];
    __syncthreads();

    const int warp = tid >> 5;
    const int lane = tid & 31;
    const int row  = blockIdx.x * 8 + warp;
    const float* hr = h + (size_t)row * HIDD;

    float acc[PEXP];
#pragma unroll
    for (int p = 0; p < PEXP; p++) acc[p] = 0.0f;
#pragma unroll
    for (int i = 0; i < HIDD / 32; i++) {
        const float hv = hr[i * 32 + lane];
#pragma unroll
        for (int p = 0; p < PEXP; p++)
            acc[p] = fmaf(hv, ws[p * HIDD + i * 32 + lane], acc[p]);
    }
#pragma unroll
    for (int p = 0; p < PEXP; p++)
#pragma unroll
        for (int off = 16; off > 0; off >>= 1)
            acc[p] += __shfl_xor_sync(0xffffffffu, acc[p], off);

    float l[PEXP], m = -1e30f;
#pragma unroll
    for (int p = 0; p < PEXP; p++) { l[p] = acc[p] + gb2[p]; m = fmaxf(m, l[p]); }
    float s = 0.0f;
#pragma unroll
    for (int p = 0; p < PEXP; p++) { l[p] = expf(l[p] - m); s += l[p]; }
    const float inv = 1.0f / s;

    float myv = 0.0f;
#pragma unroll
    for (int p = 0; p < PEXP; p++)
        if (lane == p) myv = l[p] * inv;
    if (lane < PEXP) blend[(size_t)row * PEXP + lane] = myv;
}

// ======================= host launch =======================================
extern "C" void kernel_launch(void* const* d_in, const int* in_sizes, int n_in,
                              void* d_out, int out_size)
{
    const float* obs = (const float*)d_in[0];
    const float* gw0 = (const float*)d_in[1];
    const float* gb0 = (const float*)d_in[2];
    const float* gw1 = (const float*)d_in[3];
    const float* gb1 = (const float*)d_in[4];
    const float* gw2 = (const float*)d_in[5];
    const float* gb2 = (const float*)d_in[6];
    const float* ew0 = (const float*)d_in[7];
    const float* eb0 = (const float*)d_in[8];
    const float* ew1 = (const float*)d_in[9];
    const float* eb1 = (const float*)d_in[10];
    const float* ew2 = (const float*)d_in[11];
    const float* eb2 = (const float*)d_in[12];
    float* out = (float*)d_out;

    __nv_bfloat16 *gw0h, *gw0l, *gw1h, *gw1l, *ew0h, *ew0l, *ew1h, *ew1l, *ew2h, *ew2l;
    float *bufA, *bufB, *blend;
    cudaGetSymbolAddress((void**)&gw0h, d_gw0_h);
    cudaGetSymbolAddress((void**)&gw0l, d_gw0_l);
    cudaGetSymbolAddress((void**)&gw1h, d_gw1_h);
    cudaGetSymbolAddress((void**)&gw1l, d_gw1_l);
    cudaGetSymbolAddress((void**)&ew0h, d_ew0_h);
    cudaGetSymbolAddress((void**)&ew0l, d_ew0_l);
    cudaGetSymbolAddress((void**)&ew1h, d_ew1_h);
    cudaGetSymbolAddress((void**)&ew1l, d_ew1_l);
    cudaGetSymbolAddress((void**)&ew2h, d_ew2_h);
    cudaGetSymbolAddress((void**)&ew2l, d_ew2_l);
    cudaGetSymbolAddress((void**)&bufA, d_bufA);
    cudaGetSymbolAddress((void**)&bufB, d_bufB);
    cudaGetSymbolAddress((void**)&blend, d_blend);

    static const int S128 = 8192 + 2 * (16384 + 128 * 128);  // 73728
    static const int S64  = 8192 + 2 * (16384 + 64 * 128);   // 57344
    cudaFuncSetAttribute(moe_gemm<1, 0, 128, 256>, cudaFuncAttributeMaxDynamicSharedMemorySize, S128);
    cudaFuncSetAttribute(moe_gemm<1, 0, 128, 512>, cudaFuncAttributeMaxDynamicSharedMemorySize, S128);
    cudaFuncSetAttribute(moe_gemm<8, 0, 128, 256>, cudaFuncAttributeMaxDynamicSharedMemorySize, S128);
    cudaFuncSetAttribute(moe_gemm<8, 0, 128, 512>, cudaFuncAttributeMaxDynamicSharedMemorySize, S128);
    cudaFuncSetAttribute(moe_gemm<8, 1, 64, 512>,  cudaFuncAttributeMaxDynamicSharedMemorySize, S64);

    // split weights to bf16 hi/lo
    cvt_hl<<<128, 256>>>(gw0, gw0h, gw0l, HIDD * OBSD);
    cvt_hl<<<128, 256>>>(gw1, gw1h, gw1l, HIDD * HIDD);
    cvt_hl<<<256, 256>>>(ew0, ew0h, ew0l, PEXP * HIDD * OBSD);
    cvt_hl<<<512, 256>>>(ew1, ew1h, ew1l, PEXP * HIDD * HIDD);
    cvt_hl<<<128, 256>>>(ew2, ew2h, ew2l, PEXP * 2 * ACTD * HIDD);

    const dim3 blk(256);
    const dim3 g512(HIDD / 128, B_ / 128);   // (4, 64)
    // gate trunk
    moe_gemm<1, 0, 128, 256><<<g512, blk, S128>>>(obs,  gw0h, gw0l, gb0, nullptr, bufA, HIDD);
    moe_gemm<1, 0, 128, 512><<<g512, blk, S128>>>(bufA, gw1h, gw1l, gb1, nullptr, bufB, HIDD);
    gate2_softmax<<<B_ / 8, blk>>>(bufB, gw2, gb2, blend);
    // blended experts (blend folded into A)
    moe_gemm<8, 0, 128, 256><<<g512, blk, S128>>>(obs,  ew0h, ew0l, eb0, blend, bufA, HIDD);
    moe_gemm<8, 0, 128, 512><<<g512, blk, S128>>>(bufA, ew1h, ew1l, eb1, blend, bufB, HIDD);
    moe_gemm<8, 1, 64, 512><<<dim3(1, B_ / 128), blk, S64>>>(bufB, ew2h, ew2l, eb2, blend, out, 2 * ACTD);
}

// round 4
// speedup vs baseline: 11.3127x; 2.9790x over previous
#include <cuda_runtime.h>
#include <cuda_fp16.h>
#include <cstdint>
#include <math.h>

#define B_    8192
#define OBSD  256
#define ACTD  32
#define HIDD  512
#define PEXP  8

// ======================= scratch (no allocs allowed) =======================
__device__ __align__(16) __half d_obs16[B_ * OBSD];
__device__ __align__(16) __half d_gw016[HIDD * OBSD];
__device__ __align__(16) __half d_gw116[HIDD * HIDD];
__device__ __align__(16) __half d_ew016[PEXP * HIDD * OBSD];
__device__ __align__(16) __half d_ew116[PEXP * HIDD * HIDD];
__device__ __align__(16) __half d_ew216[PEXP * 2 * ACTD * HIDD];
__device__ __align__(16) __half d_act0[B_ * HIDD];
__device__ __align__(16) __half d_act1[B_ * HIDD];
__device__ __align__(16) __half d_actA[B_ * HIDD];
__device__ __align__(16) __half d_actB[B_ * HIDD];
__device__ __align__(16) float d_blend[B_ * PEXP];

// ======================= low-level helpers =================================
__device__ __forceinline__ uint32_t smem_u32(const void* p) {
    uint32_t a;
    asm("{ .reg .u64 t; cvta.to.shared.u64 t, %1; cvt.u32.u64 %0, t; }" : "=r"(a) : "l"(p));
    return a;
}
#define CP_ASYNC16(dst, src) \
    asm volatile("cp.async.cg.shared.global [%0], [%1], 16;" :: "r"(dst), "l"(src))
#define CP_COMMIT() asm volatile("cp.async.commit_group;" ::: "memory")
#define CP_WAIT_1() asm volatile("cp.async.wait_group 1;" ::: "memory")

__device__ __forceinline__ void ldsm4(uint32_t* r, uint32_t addr) {
    asm volatile("ldmatrix.sync.aligned.m8n8.x4.shared.b16 {%0,%1,%2,%3}, [%4];"
                 : "=r"(r[0]), "=r"(r[1]), "=r"(r[2]), "=r"(r[3]) : "r"(addr));
}
__device__ __forceinline__ void mma16816(float* c, const uint32_t* a, uint32_t b0, uint32_t b1) {
    asm volatile(
        "mma.sync.aligned.m16n8k16.row.col.f32.f16.f16.f32 "
        "{%0,%1,%2,%3}, {%4,%5,%6,%7}, {%8,%9}, {%0,%1,%2,%3};"
        : "+f"(c[0]), "+f"(c[1]), "+f"(c[2]), "+f"(c[3])
        : "r"(a[0]), "r"(a[1]), "r"(a[2]), "r"(a[3]), "r"(b0), "r"(b1));
}

// ======================= fp32 -> fp16 convert ==============================
__global__ __launch_bounds__(256)
void cvt16(const float* __restrict__ src, __half* __restrict__ dst, int n4) {
    int i = blockIdx.x * blockDim.x + threadIdx.x;
    const int stride = gridDim.x * blockDim.x;
    for (; i < n4; i += stride) {
        const float4 v = *(const float4*)&src[i * 4];
        __half2 h0 = __floats2half2_rn(v.x, v.y);
        __half2 h1 = __floats2half2_rn(v.z, v.w);
        *(uint2*)&dst[i * 4] = make_uint2(*(uint32_t*)&h0, *(uint32_t*)&h1);
    }
}

// ======================= fp16 blended MoE GEMM =============================
// Y[m,n] = epi( sum_p blend[m,p] * ( A[m,:] . W[p,n,:] + bias[p,n] ) )
// A, W fp16; fp32 MMA accumulation; blend folded in registers at expert
// boundaries. 3-stage cp.async pipeline, BK=64, one __syncthreads per chunk.
// smem tile rows: 128B (64 fp16), 16B chunks XOR-swizzled: phys = ch ^ (row&7).
template <int NEXP, int EPI, int BM, int BN, int K>
__global__ __launch_bounds__(256, 1)
void moe_gemm(const __half* __restrict__ A, const __half* __restrict__ W,
              const float* __restrict__ bias, const float* __restrict__ blend,
              __half* __restrict__ Yh, float* __restrict__ Yf, int NTOT)
{
    constexpr int NCK   = K / 64;
    constexpr int NCH   = NEXP * NCK;
    constexpr int MT    = BM / 64;          // m16 tiles per warp (4 m-warps)
    constexpr int NT    = BN / 32;          // n16 tiles per warp (2 n-warps)
    constexpr int AIT   = BM / 32;          // A cp.async iters (BM*8 chunks / 256)
    constexpr int BIT_  = BN / 32;
    constexpr int STAGE = BM * 128 + BN * 128;

    extern __shared__ __align__(16) char smem[];
    float* bias_s  = (float*)smem;           // [NEXP*BN]   (<= 4KB)
    float* blend_s = (float*)(smem + 4096);  // [BM*8]      (<= 4KB)
    const uint32_t sb = smem_u32(smem);

    const int tid = threadIdx.x;
    const int wid = tid >> 5;
    const int t   = tid & 31;
    const int row0 = blockIdx.y * BM;
    const int n0   = blockIdx.x * BN;

    for (int i = tid; i < NEXP * BN; i += 256)
        bias_s[i] = bias[(size_t)(i / BN) * NTOT + n0 + (i % BN)];
    if (NEXP > 1)
        for (int i = tid; i < BM * 8; i += 256)
            blend_s[i] = blend[(size_t)(row0 + (i >> 3)) * PEXP + (i & 7)];
    __syncthreads();

    const int wm = wid >> 1, wn = wid & 1;
    const int aro = t & 15;                  // A row within m16
    const int akg = t >> 4;                  // A 16B-chunk half of k16
    const int bno = ((t >> 4) << 3) + (t & 7);  // B n within n16
    const int bkg = (t >> 3) & 1;            // B 16B-chunk half of k16
    const int tq  = t >> 2, tr = t & 3;

    float acc[MT][2 * NT][4];
    float accT[MT][2 * NT][4];
#pragma unroll
    for (int a = 0; a < MT; a++)
#pragma unroll
        for (int b = 0; b < 2 * NT; b++)
#pragma unroll
            for (int q = 0; q < 4; q++) { acc[a][b][q] = 0.0f; if (NEXP > 1) accT[a][b][q] = 0.0f; }

    auto issueLoads = [&](int ci, int s) {
        const int p  = ci / NCK;
        const int kk = (ci % NCK) * 64;
        const uint32_t stA = sb + 8192 + (uint32_t)s * STAGE;
        const uint32_t stB = stA + BM * 128;
#pragma unroll
        for (int it = 0; it < AIT; it++) {
            const int idx = tid + it * 256;
            const int r = idx >> 3, ch = idx & 7;
            const __half* src = A + (size_t)(row0 + r) * K + kk + ch * 8;
            CP_ASYNC16(stA + r * 128 + ((ch ^ (r & 7)) << 4), src);
        }
#pragma unroll
        for (int it = 0; it < BIT_; it++) {
            const int idx = tid + it * 256;
            const int r = idx >> 3, ch = idx & 7;
            const __half* src = W + ((size_t)p * NTOT + n0 + r) * K + kk + ch * 8;
            CP_ASYNC16(stB + r * 128 + ((ch ^ (r & 7)) << 4), src);
        }
    };

    auto mmaStage = [&](int s) {
        const uint32_t stA = sb + 8192 + (uint32_t)s * STAGE;
        const uint32_t stB = stA + BM * 128;
#pragma unroll
        for (int kc = 0; kc < 4; kc++) {
            uint32_t a[MT][4];
#pragma unroll
            for (int mt = 0; mt < MT; mt++) {
                const int row = wm * (MT * 16) + mt * 16 + aro;
                const int ch = kc * 2 + akg;
                ldsm4(a[mt], stA + row * 128 + ((ch ^ (row & 7)) << 4));
            }
            uint32_t b[NT][4];
#pragma unroll
            for (int nt = 0; nt < NT; nt++) {
                const int n = wn * (NT * 16) + nt * 16 + bno;
                const int ch = kc * 2 + bkg;
                ldsm4(b[nt], stB + n * 128 + ((ch ^ (n & 7)) << 4));
            }
#pragma unroll
            for (int mt = 0; mt < MT; mt++)
#pragma unroll
                for (int nt = 0; nt < NT; nt++) {
                    mma16816(acc[mt][2 * nt + 0], a[mt], b[nt][0], b[nt][1]);
                    mma16816(acc[mt][2 * nt + 1], a[mt], b[nt][2], b[nt][3]);
                }
        }
    };

    // -------- pipeline: 3 stages, one sync per chunk --------
    issueLoads(0, 0); CP_COMMIT();
    issueLoads(1, 1); CP_COMMIT();

#pragma unroll 1
    for (int ci = 0; ci < NCH; ci++) {
        CP_WAIT_1();
        __syncthreads();
        if (ci + 2 < NCH) issueLoads(ci + 2, (ci + 2) % 3);
        CP_COMMIT();
        mmaStage(ci % 3);
        if (NEXP > 1 && ((ci + 1) % NCK == 0)) {
            const int p = ci / NCK;
#pragma unroll
            for (int mt = 0; mt < MT; mt++) {
                const int rb = wm * (MT * 16) + mt * 16 + tq;
                const float bl0 = blend_s[rb * 8 + p];
                const float bl1 = blend_s[(rb + 8) * 8 + p];
#pragma unroll
                for (int nn = 0; nn < 2 * NT; nn++) {
                    accT[mt][nn][0] = fmaf(bl0, acc[mt][nn][0], accT[mt][nn][0]);
                    accT[mt][nn][1] = fmaf(bl0, acc[mt][nn][1], accT[mt][nn][1]);
                    accT[mt][nn][2] = fmaf(bl1, acc[mt][nn][2], accT[mt][nn][2]);
                    accT[mt][nn][3] = fmaf(bl1, acc[mt][nn][3], accT[mt][nn][3]);
                    acc[mt][nn][0] = 0.0f; acc[mt][nn][1] = 0.0f;
                    acc[mt][nn][2] = 0.0f; acc[mt][nn][3] = 0.0f;
                }
            }
        }
    }

    // -------- epilogue --------
#pragma unroll
    for (int mt = 0; mt < MT; mt++) {
#pragma unroll
        for (int h = 0; h < 2; h++) {
            const int r = wm * (MT * 16) + mt * 16 + tq + h * 8;
            float blv[PEXP];
            if (NEXP > 1) {
#pragma unroll
                for (int p = 0; p < PEXP; p++) blv[p] = blend_s[r * 8 + p];
            }
#pragma unroll
            for (int nn = 0; nn < 2 * NT; nn++) {
                const int col = wn * (NT * 16) + (nn >> 1) * 16 + (nn & 1) * 8 + tr * 2;
                float v0, v1;
                if (NEXP == 1) {
                    v0 = acc[mt][nn][h * 2 + 0] + bias_s[col];
                    v1 = acc[mt][nn][h * 2 + 1] + bias_s[col + 1];
                } else {
                    float b0 = 0.0f, b1 = 0.0f;
#pragma unroll
                    for (int p = 0; p < PEXP; p++) {
                        b0 = fmaf(blv[p], bias_s[p * BN + col], b0);
                        b1 = fmaf(blv[p], bias_s[p * BN + col + 1], b1);
                    }
                    v0 = accT[mt][nn][h * 2 + 0] + b0;
                    v1 = accT[mt][nn][h * 2 + 1] + b1;
                }
                if (EPI == 0) {
                    v0 = fmaxf(v0, 0.0f); v1 = fmaxf(v1, 0.0f);
                    __half2 hv = __floats2half2_rn(v0, v1);
                    *(uint32_t*)&Yh[(size_t)(row0 + r) * NTOT + n0 + col] = *(uint32_t*)&hv;
                } else {
                    if (col >= 32)     v0 = expf(3.5f * tanhf(v0) - 1.5f);
                    if (col + 1 >= 32) v1 = expf(3.5f * tanhf(v1) - 1.5f);
                    *(float2*)&Yf[(size_t)(row0 + r) * NTOT + n0 + col] = make_float2(v0, v1);
                }
            }
        }
    }
}

// ======================= gate head + softmax ===============================
__global__ __launch_bounds__(256)
void gate2_softmax(const __half* __restrict__ h, const float* __restrict__ gw2,
                   const float* __restrict__ gb2, float* __restrict__ blend)
{
    __shared__ float ws[PEXP * HIDD];
    const int tid = threadIdx.x;
    for (int i = tid; i < PEXP * HIDD; i += blockDim.x) ws[i] = gw2[i];
    __syncthreads();

    const int warp = tid >> 5;
    const int lane = tid & 31;
    const int row  = blockIdx.x * 8 + warp;
    const __half* hr = h + (size_t)row * HIDD;

    float acc[PEXP];
#pragma unroll
    for (int p = 0; p < PEXP; p++) acc[p] = 0.0f;
#pragma unroll
    for (int i = 0; i < HIDD / 32; i++) {
        const float hv = __half2float(hr[i * 32 + lane]);
#pragma unroll
        for (int p = 0; p < PEXP; p++)
            acc[p] = fmaf(hv, ws[p * HIDD + i * 32 + lane], acc[p]);
    }
#pragma unroll
    for (int p = 0; p < PEXP; p++)
#pragma unroll
        for (int off = 16; off > 0; off >>= 1)
            acc[p] += __shfl_xor_sync(0xffffffffu, acc[p], off);

    float l[PEXP], m = -1e30f;
#pragma unroll
    for (int p = 0; p < PEXP; p++) { l[p] = acc[p] + gb2[p]; m = fmaxf(m, l[p]); }
    float s = 0.0f;
#pragma unroll
    for (int p = 0; p < PEXP; p++) { l[p] = expf(l[p] - m); s += l[p]; }
    const float inv = 1.0f / s;

    float myv = 0.0f;
#pragma unroll
    for (int p = 0; p < PEXP; p++)
        if (lane == p) myv = l[p] * inv;
    if (lane < PEXP) blend[(size_t)row * PEXP + lane] = myv;
}

// ======================= host launch =======================================
extern "C" void kernel_launch(void* const* d_in, const int* in_sizes, int n_in,
                              void* d_out, int out_size)
{
    const float* obs = (const float*)d_in[0];
    const float* gw0 = (const float*)d_in[1];
    const float* gb0 = (const float*)d_in[2];
    const float* gw1 = (const float*)d_in[3];
    const float* gb1 = (const float*)d_in[4];
    const float* gw2 = (const float*)d_in[5];
    const float* gb2 = (const float*)d_in[6];
    const float* ew0 = (const float*)d_in[7];
    const float* eb0 = (const float*)d_in[8];
    const float* ew1 = (const float*)d_in[9];
    const float* eb1 = (const float*)d_in[10];
    const float* ew2 = (const float*)d_in[11];
    const float* eb2 = (const float*)d_in[12];
    float* out = (float*)d_out;

    __half *obs16, *gw016, *gw116, *ew016, *ew116, *ew216;
    __half *act0, *act1, *actA, *actB;
    float* blend;
    cudaGetSymbolAddress((void**)&obs16, d_obs16);
    cudaGetSymbolAddress((void**)&gw016, d_gw016);
    cudaGetSymbolAddress((void**)&gw116, d_gw116);
    cudaGetSymbolAddress((void**)&ew016, d_ew016);
    cudaGetSymbolAddress((void**)&ew116, d_ew116);
    cudaGetSymbolAddress((void**)&ew216, d_ew216);
    cudaGetSymbolAddress((void**)&act0, d_act0);
    cudaGetSymbolAddress((void**)&act1, d_act1);
    cudaGetSymbolAddress((void**)&actA, d_actA);
    cudaGetSymbolAddress((void**)&actB, d_actB);
    cudaGetSymbolAddress((void**)&blend, d_blend);

    static const int S128 = 8192 + 3 * (128 * 128 + 128 * 128);  // 106496
    static const int S64  = 8192 + 3 * (64 * 128 + 64 * 128);    // 57344
    cudaFuncSetAttribute(moe_gemm<1, 0, 128, 128, 256>, cudaFuncAttributeMaxDynamicSharedMemorySize, S128);
    cudaFuncSetAttribute(moe_gemm<1, 0, 128, 128, 512>, cudaFuncAttributeMaxDynamicSharedMemorySize, S128);
    cudaFuncSetAttribute(moe_gemm<8, 0, 128, 128, 256>, cudaFuncAttributeMaxDynamicSharedMemorySize, S128);
    cudaFuncSetAttribute(moe_gemm<8, 0, 128, 128, 512>, cudaFuncAttributeMaxDynamicSharedMemorySize, S128);
    cudaFuncSetAttribute(moe_gemm<8, 1, 64, 64, 512>,   cudaFuncAttributeMaxDynamicSharedMemorySize, S64);

    // converts (fp32 -> fp16)
    cvt16<<<512, 256>>>(obs, obs16, B_ * OBSD / 4);
    cvt16<<<128, 256>>>(gw0, gw016, HIDD * OBSD / 4);
    cvt16<<<128, 256>>>(gw1, gw116, HIDD * HIDD / 4);
    cvt16<<<256, 256>>>(ew0, ew016, PEXP * HIDD * OBSD / 4);
    cvt16<<<512, 256>>>(ew1, ew116, PEXP * HIDD * HIDD / 4);
    cvt16<<<128, 256>>>(ew2, ew216, PEXP * 2 * ACTD * HIDD / 4);

    const dim3 blk(256);
    const dim3 g512(HIDD / 128, B_ / 128);   // (4, 64)
    // gate trunk
    moe_gemm<1, 0, 128, 128, 256><<<g512, blk, S128>>>(obs16, gw016, gb0, nullptr, act0, nullptr, HIDD);
    moe_gemm<1, 0, 128, 128, 512><<<g512, blk, S128>>>(act0, gw116, gb1, nullptr, act1, nullptr, HIDD);
    gate2_softmax<<<B_ / 8, blk>>>(act1, gw2, gb2, blend);
    // blended experts (blend folded in registers at expert boundaries)
    moe_gemm<8, 0, 128, 128, 256><<<g512, blk, S128>>>(obs16, ew016, eb0, blend, actA, nullptr, HIDD);
    moe_gemm<8, 0, 128, 128, 512><<<g512, blk, S128>>>(actA, ew116, eb1, blend, actB, nullptr, HIDD);
    moe_gemm<8, 1, 64, 64, 512><<<dim3(1, B_ / 64), blk, S64>>>(actB, ew216, eb2, blend, nullptr, out, 2 * ACTD);
}